// round 7
// baseline (speedup 1.0000x reference)
#include <cuda_runtime.h>
#include <math.h>
#include <stdint.h>

#define FIN 256
#define ND  16

// scratch (static device arrays — no allocations)
__device__ float g_Gr[FIN*ND];
__device__ float g_Gi[FIN*ND];
__device__ float g_A2[FIN*ND];          // paired layout: [k/2][n][2] = {A[2kp][n], A[2kp+1][n]}
__device__ float g_c [ND];
__device__ float g_kw[9*ND];            // BN-folded depthwise weights [tap][d]
__device__ float g_kb[ND];              // BN-folded bias
__device__ float g_y [2*256*256*ND];    // intermediate y grid (8 MB)

__device__ __forceinline__ uint32_t smem_u32(const void* p) {
    uint32_t a;
    asm("{ .reg .u64 t; cvta.to.shared.u64 t, %1; cvt.u32.u64 %0, t; }"
        : "=r"(a) : "l"(p));
    return a;
}
__device__ __forceinline__ void cp_async16(uint32_t dst, const void* src) {
    asm volatile("cp.async.cg.shared.global [%0], [%1], 16;" :: "r"(dst), "l"(src));
}
// packed dual-FMA: d.lo += a.lo*b.lo; d.hi += a.hi*b.hi  (SASS FFMA2)
__device__ __forceinline__ void ffma2(unsigned long long& d,
                                      unsigned long long a,
                                      unsigned long long b) {
    asm("fma.rn.f32x2 %0, %1, %2, %0;" : "+l"(d) : "l"(a), "l"(b));
}
__device__ __forceinline__ float2 u2f2(unsigned long long u) {
    float2 f;
    asm("mov.b64 {%0, %1}, %2;" : "=f"(f.x), "=f"(f.y) : "l"(u));
    return f;
}

// ---------------------------------------------------------------------------
// pre1: G[k,d] = sum_m e^{-2pi i m k/256} (Wr[m,d] + i Wi[m,d])
// ---------------------------------------------------------------------------
__global__ void __launch_bounds__(256) pre1_kernel(const float* __restrict__ Wr,
                                                   const float* __restrict__ Wi)
{
    __shared__ float ct[256], st[256];
    int tid = threadIdx.x;
    {
        float ang = 6.283185307179586f * (float)tid / 256.0f;
        float s, c; sincosf(ang, &s, &c);
        ct[tid] = c; st[tid] = s;
    }
    __syncthreads();

    int i = blockIdx.x * 256 + tid;      // 0..4095
    int k = i >> 4, d = i & 15;
    float grA = 0.f, giA = 0.f, grB = 0.f, giB = 0.f;
#pragma unroll 4
    for (int m = 0; m < 256; m += 2) {
        int t0 = (m * k) & 255;
        int t1 = ((m + 1) * k) & 255;
        float c0 = ct[t0], s0 = st[t0];
        float c1 = ct[t1], s1 = st[t1];
        float wr0 = Wr[m * 16 + d],       wi0 = Wi[m * 16 + d];
        float wr1 = Wr[(m + 1) * 16 + d], wi1 = Wi[(m + 1) * 16 + d];
        grA = fmaf(c0, wr0, fmaf(s0, wi0, grA));
        giA = fmaf(c0, wi0, fmaf(-s0, wr0, giA));
        grB = fmaf(c1, wr1, fmaf(s1, wi1, grB));
        giB = fmaf(c1, wi1, fmaf(-s1, wr1, giB));
    }
    g_Gr[i] = grA + grB;
    g_Gi[i] = giA + giB;
}

// ---------------------------------------------------------------------------
// pre2: A[k,n] = (1/16) sum_d [Gr cos(2pi nd/16) - Gi sin(2pi nd/16)]
//       stored into paired layout g_A2[(k>>1)*32 + n*2 + (k&1)].
//       Also c[n], BN-folded conv weights/bias.
// ---------------------------------------------------------------------------
__global__ void __launch_bounds__(256) pre2_kernel(const float* __restrict__ br,
                                                   const float* __restrict__ bi,
                                                   const float* __restrict__ dwk,
                                                   const float* __restrict__ dwb,
                                                   const float* __restrict__ gamma,
                                                   const float* __restrict__ beta,
                                                   const float* __restrict__ mmean,
                                                   const float* __restrict__ mvar)
{
    __shared__ float c16[16], s16[16];
    int tid = threadIdx.x;
    if (tid < 16) {
        float ang = 6.283185307179586f * (float)tid / 16.0f;
        float s, c; sincosf(ang, &s, &c);
        c16[tid] = c; s16[tid] = s;
    }
    __syncthreads();

    int i = blockIdx.x * 256 + tid;      // 0..4095
    int k = i >> 4, n = i & 15;
    float acc = 0.f;
#pragma unroll
    for (int d = 0; d < 16; d++) {
        int u = (n * d) & 15;
        acc = fmaf(g_Gr[k * 16 + d], c16[u], fmaf(-g_Gi[k * 16 + d], s16[u], acc));
    }
    g_A2[(k >> 1) * 32 + n * 2 + (k & 1)] = acc * 0.0625f;

    if (blockIdx.x == 0) {
        if (tid < 16) {
            float cc = 0.f;
#pragma unroll
            for (int d = 0; d < 16; d++) {
                int u = (tid * d) & 15;
                cc += (br[d] - bi[d]) * c16[u] - (br[d] + bi[d]) * s16[u];
            }
            g_c[tid] = cc * 0.0625f;
            float scale = gamma[tid] * rsqrtf(mvar[tid] + 1e-5f);
            g_kb[tid] = (dwb[tid] - mmean[tid]) * scale + beta[tid];
        }
        if (tid < 144) {
            int d = tid & 15;
            float scale = gamma[d] * rsqrtf(mvar[d] + 1e-5f);
            g_kw[tid] = dwk[tid] * scale;
        }
    }
}

// ---------------------------------------------------------------------------
// main GEMM via packed f32x2 FMA (FFMA2): even/odd k-split partial sums.
// Structure identical to the best round (R4): block = 128 thr = 4 warps,
// warp owns 64 patches, per-warp private 2x4KB cp.async double-buffer,
// XOR-swizzled smem, no block barriers in mainloop.
// acc[jj][t] is f32x2 = (sum over even k, sum over odd k); merged at the end.
// FMA-pipe work per warp-row: 256 FFMA2 (was 512 FFMA) -> floor halves.
// ---------------------------------------------------------------------------
__global__ void __launch_bounds__(128, 4) fno_gemm_kernel(const float* __restrict__ x)
{
    __shared__ float xs[4][2][1024];     // [warp][buf][64 patches * 16 floats]
    __shared__ float As[FIN * ND];       // paired A2: pair idx = kp*16 + n

    int t    = threadIdx.x;
    int w    = t >> 5;
    int lane = t & 31;
    int bid  = blockIdx.x;               // b*256 + ph
    int b    = bid >> 8;
    int ph   = bid & 255;

    // this warp's slice of the image row: 64 patches * 16 floats = 1024 floats
    const float* xbase = x + (size_t)(b * 4096 + ph * 16) * 4096 + w * 1024;

    uint32_t buf[2] = { smem_u32(&xs[w][0][0]), smem_u32(&xs[w][1][0]) };
    uint32_t dstoff[8];
#pragma unroll
    for (int it = 0; it < 8; it++) {
        int g4 = lane + it * 32;         // chunk index within warp slice 0..255
        int p  = g4 >> 2, c = g4 & 3;
        int cc = c ^ ((p >> 1) & 3);
        dstoff[it] = (uint32_t)((p * 4 + cc) << 4);
    }

    // kick off row 0
    {
        const char* src = (const char*)xbase;
#pragma unroll
        for (int it = 0; it < 8; it++)
            cp_async16(buf[0] + dstoff[it], src + ((lane + it * 32) << 4));
        asm volatile("cp.async.commit_group;");
    }

    {   // stage paired A into smem (4096 floats) — overlaps with row-0 cp.async
        const float4* A4  = (const float4*)g_A2;
        float4*       As4 = (float4*)As;
#pragma unroll
        for (int it = 0; it < 8; it++)
            As4[t + it * 128] = A4[t + it * 128];
    }
    __syncthreads();                     // As visible (once, pre-loop)

    int cg  = lane & 3;
    int pg  = lane >> 2;                 // 0..7
    int swz = (pg >> 1) & 3;             // read-side swizzle key
    unsigned long long acc[8][4];
#pragma unroll
    for (int jj = 0; jj < 8; jj++)
#pragma unroll
        for (int tt = 0; tt < 4; tt++) acc[jj][tt] = 0ull;

    const unsigned long long* As2 = (const unsigned long long*)As;  // pair units

    for (int kr = 0; kr < 16; kr++) {
        if (kr < 15) {
            uint32_t dbuf = buf[(kr + 1) & 1];
            const char* src = (const char*)(xbase + (size_t)(kr + 1) * 4096);
#pragma unroll
            for (int it = 0; it < 8; it++)
                cp_async16(dbuf + dstoff[it], src + ((lane + it * 32) << 4));
            asm volatile("cp.async.commit_group;");
            asm volatile("cp.async.wait_group 1;");   // row kr landed
        } else {
            asm volatile("cp.async.wait_group 0;");
        }
        __syncwarp();                    // all lanes' chunks of row kr visible

        const float* xb = xs[w][kr & 1];
#pragma unroll
        for (int kc4 = 0; kc4 < 4; kc4++) {
            int kp0 = kr * 8 + kc4 * 2;  // k-pair index of xv.{x,y}
            const unsigned long long* Ab = As2 + kp0 * 16 + cg * 4;
            ulonglong2 U01 = *(const ulonglong2*)(Ab);        // kp0:   n0, n1
            ulonglong2 U23 = *(const ulonglong2*)(Ab + 2);    // kp0:   n2, n3
            ulonglong2 V01 = *(const ulonglong2*)(Ab + 16);   // kp0+1: n0, n1
            ulonglong2 V23 = *(const ulonglong2*)(Ab + 18);   // kp0+1: n2, n3
            int co = (kc4 ^ swz) << 2;   // swizzled float offset within patch
#pragma unroll
            for (int jj = 0; jj < 8; jj++) {
                int p = jj * 8 + pg;     // local patch 0..63
                ulonglong2 X = *(const ulonglong2*)&xb[p * 16 + co];
                // X.x = {x[2kp0], x[2kp0+1]},  X.y = {x[2kp0+2], x[2kp0+3]}
                ffma2(acc[jj][0], X.x, U01.x);
                ffma2(acc[jj][1], X.x, U01.y);
                ffma2(acc[jj][2], X.x, U23.x);
                ffma2(acc[jj][3], X.x, U23.y);
                ffma2(acc[jj][0], X.y, V01.x);
                ffma2(acc[jj][1], X.y, V01.y);
                ffma2(acc[jj][2], X.y, V23.x);
                ffma2(acc[jj][3], X.y, V23.y);
            }
        }
        __syncwarp();                    // buffer (kr&1) free before re-issue at kr+1
    }

    float4 cc = ((const float4*)g_c)[cg];
    float4* y4 = (float4*)g_y;
#pragma unroll
    for (int jj = 0; jj < 8; jj++) {
        int gp = bid * 256 + w * 64 + jj * 8 + pg;   // global patch
        float2 a0 = u2f2(acc[jj][0]);
        float2 a1 = u2f2(acc[jj][1]);
        float2 a2 = u2f2(acc[jj][2]);
        float2 a3 = u2f2(acc[jj][3]);
        float4 o;
        o.x = a0.x + a0.y + cc.x;
        o.y = a1.x + a1.y + cc.y;
        o.z = a2.x + a2.y + cc.z;
        o.w = a3.x + a3.y + cc.w;
        y4[gp * 4 + cg] = o;
    }
}

// ---------------------------------------------------------------------------
// depthwise 3x3 SAME conv (BN folded) at resized positions.
// Two vertical outputs per thread: i = 2*iq and 2*iq+1 share row 4*iq+2.
// ---------------------------------------------------------------------------
__global__ void __launch_bounds__(128) conv_resize_kernel(float* __restrict__ out)
{
    int lin = blockIdx.x * 128 + threadIdx.x;   // 0..65535
    int cg = lin & 3;
    int j  = (lin >> 2) & 127;
    int iq = (lin >> 9) & 63;
    int b  = lin >> 15;

    int i0 = 2 * iq;
    int c1 = 2 * j + 1;
    int rbase = 4 * iq;                          // = (2*i0+1) - 1

    const float4* y4  = (const float4*)g_y;
    const float4* kw4 = (const float4*)g_kw;
    float4 kb = ((const float4*)g_kb)[cg];
    float4 s0 = kb, s1 = kb;

#pragma unroll
    for (int rr = 0; rr < 5; rr++) {
        int r = rbase + rr;
        if (r > 255) continue;                   // only rr=4 at iq=63
#pragma unroll
        for (int dx = -1; dx <= 1; dx++) {
            int c = c1 + dx;                     // c >= 0 always
            if (c > 255) continue;
            float4 v = y4[((b * 256 + r) * 256 + c) * 4 + cg];
            if (rr < 3) {                        // output i0: taps rows rr=0,1,2
                float4 w = kw4[(rr * 3 + (dx + 1)) * 4 + cg];
                s0.x = fmaf(v.x, w.x, s0.x);
                s0.y = fmaf(v.y, w.y, s0.y);
                s0.z = fmaf(v.z, w.z, s0.z);
                s0.w = fmaf(v.w, w.w, s0.w);
            }
            if (rr >= 2) {                       // output i0+1: taps rows rr=2,3,4
                float4 w = kw4[((rr - 2) * 3 + (dx + 1)) * 4 + cg];
                s1.x = fmaf(v.x, w.x, s1.x);
                s1.y = fmaf(v.y, w.y, s1.y);
                s1.z = fmaf(v.z, w.z, s1.z);
                s1.w = fmaf(v.w, w.w, s1.w);
            }
        }
    }
    float4* o4 = (float4*)out;
    o4[((b * 128 + i0) * 128 + j) * 4 + cg]       = s0;
    o4[((b * 128 + i0 + 1) * 128 + j) * 4 + cg]   = s1;
}

// ---------------------------------------------------------------------------
extern "C" void kernel_launch(void* const* d_in, const int* in_sizes, int n_in,
                              void* d_out, int out_size)
{
    const float* x     = (const float*)d_in[0];
    const float* Wr    = (const float*)d_in[1];
    const float* br    = (const float*)d_in[2];
    const float* Wi    = (const float*)d_in[3];
    const float* bi    = (const float*)d_in[4];
    const float* dwk   = (const float*)d_in[5];
    const float* dwb   = (const float*)d_in[6];
    const float* gamma = (const float*)d_in[7];
    const float* beta  = (const float*)d_in[8];
    const float* mmean = (const float*)d_in[9];
    const float* mvar  = (const float*)d_in[10];

    pre1_kernel<<<16, 256>>>(Wr, Wi);
    pre2_kernel<<<16, 256>>>(br, bi, dwk, dwb, gamma, beta, mmean, mvar);
    fno_gemm_kernel<<<512, 128>>>(x);
    conv_resize_kernel<<<512, 128>>>((float*)d_out);
}